// round 9
// baseline (speedup 1.0000x reference)
#include <cuda_runtime.h>
#include <cuda_fp16.h>

// Problem constants
#define NN 100000
#define EE 1600000
#define HID 128
#define NCLS 40
#define NB 391              // ceil(NN/256)

typedef unsigned long long ull;

// f32x2 packed fma (Blackwell): d = a*b+c elementwise on packed fp32 pairs
__device__ __forceinline__ ull fma2(ull a, ull b, ull c) {
    ull d;
    asm("fma.rn.f32x2 %0, %1, %2, %3;" : "=l"(d) : "l"(a), "l"(b), "l"(c));
    return d;
}
__device__ __forceinline__ ull pack2(float lo, float hi) {
    ull d;
    asm("mov.b64 %0, {%1, %2};" : "=l"(d) : "f"(lo), "f"(hi));
    return d;
}
__device__ __forceinline__ float2 unpack2(ull v) {
    float lo, hi;
    asm("mov.b64 {%0, %1}, %2;" : "=f"(lo), "=f"(hi) : "l"(v));
    return make_float2(lo, hi);
}

// ---------------- device scratch (static; no cudaMalloc allowed) ----------------
__device__ __half g_tmp[(size_t)NN * HID];  // fp16 messages (pre-scaled by dinv[src])
__device__ float  g_h1[(size_t)NN * HID];   // layer-1 hidden (fp32)
__device__ float  g_dinv[NN];
__device__ int    g_deg[NN];                // in-degree incl self loop
__device__ int    g_rowptr[NN + 1];
__device__ int    g_cursor[NN];
__device__ int    g_col[EE + NN];
__device__ int    g_bsum[512];
__device__ int    g_fmt;                    // 1 = edge_index is int64, 0 = int32

// ---------------- CSR build ----------------
__global__ void k_init_deg(const int* __restrict__ ei) {
    int i = blockIdx.x * blockDim.x + threadIdx.x;
    if (i < NN) g_deg[i] = 1;   // self loop
    if (i == 0) {
        int is64 = 1;
        #pragma unroll
        for (int j = 1; j < 64; j += 2) is64 &= (ei[j] == 0);
        g_fmt = is64;
    }
}

__device__ __forceinline__ int edge_at(const void* __restrict__ ei, size_t idx) {
    if (g_fmt) return (int)((const long long*)ei)[idx];
    return ((const int*)ei)[idx];
}

__global__ void k_count(const void* __restrict__ ei) {
    int e = blockIdx.x * blockDim.x + threadIdx.x;
    if (e < EE) {
        int d = edge_at(ei, (size_t)EE + e);
        if ((unsigned)d < NN) atomicAdd(&g_deg[d], 1);
    }
}

__global__ void k_scan1() {
    __shared__ int s[256];
    int b = blockIdx.x, t = threadIdx.x;
    int i = b * 256 + t;
    int v = (i < NN) ? g_deg[i] : 0;
    s[t] = v;
    __syncthreads();
    #pragma unroll
    for (int off = 1; off < 256; off <<= 1) {
        int add = (t >= off) ? s[t - off] : 0;
        __syncthreads();
        s[t] += add;
        __syncthreads();
    }
    if (i < NN) g_rowptr[i] = s[t] - v;
    if (t == 255) g_bsum[b] = s[255];
}

__global__ void k_scan2() {
    __shared__ int s[512];
    int t = threadIdx.x;
    int v = (t < NB) ? g_bsum[t] : 0;
    s[t] = v;
    __syncthreads();
    #pragma unroll
    for (int off = 1; off < 512; off <<= 1) {
        int add = (t >= off) ? s[t - off] : 0;
        __syncthreads();
        s[t] += add;
        __syncthreads();
    }
    if (t < NB) g_bsum[t] = s[t] - v;
}

__global__ void k_scan3() {
    int b = blockIdx.x, t = threadIdx.x;
    int i = b * 256 + t;
    if (i < NN) g_rowptr[i] += g_bsum[b];
    if (i == 0) g_rowptr[NN] = EE + NN;
}

__global__ void k_selfloop() {
    int i = blockIdx.x * blockDim.x + threadIdx.x;
    if (i < NN) {
        int rp = g_rowptr[i];
        if ((unsigned)rp < (unsigned)(EE + NN)) g_col[rp] = i;
        g_cursor[i] = 1;
        g_dinv[i] = rsqrtf((float)g_deg[i]);
    }
}

__global__ void k_fill(const void* __restrict__ ei) {
    int e = blockIdx.x * blockDim.x + threadIdx.x;
    if (e < EE) {
        int s = edge_at(ei, e);
        int d = edge_at(ei, (size_t)EE + e);
        if ((unsigned)d < NN) {
            int pos = atomicAdd(&g_cursor[d], 1);
            int w = g_rowptr[d] + pos;
            int c = ((unsigned)s < NN) ? s : d;
            if ((unsigned)w < (unsigned)(EE + NN)) g_col[w] = c;
        }
    }
}

// ---------------- GEMM: g_tmp[m][n] = half((A[m][:] . W[:][n]) * dinv[m]) ----------------
// BM=128, BN=128, K chunks of 32. 256 threads, 8x8 microtile via f32x2 packed FMA.
// acc pairs along M: acc2[rp][c] = (acc[2rp][c], acc[2rp+1][c]).
template<int SRC>   // 0: read A param, 1: read g_h1
__global__ void __launch_bounds__(256, 2)
k_gemm(const float* __restrict__ A, const float* __restrict__ W) {
    __shared__ float Ws[32][128];
    __shared__ float Xs[32][132];
    const float* Ain = (SRC == 0) ? A : (const float*)g_h1;
    int t = threadIdx.x;
    int m0 = blockIdx.x * 128;
    int tx = t & 15, ty = t >> 4;
    int rb = ty * 8, cb = tx * 8;
    ull acc2[4][8];
    #pragma unroll
    for (int rp = 0; rp < 4; rp++)
        #pragma unroll
        for (int c = 0; c < 8; c++) acc2[rp][c] = 0ULL;   // (0.f,0.f)

    #pragma unroll
    for (int kc = 0; kc < HID; kc += 32) {
        #pragma unroll
        for (int i = 0; i < 4; i++) {
            int idx = t + i * 256;          // 0..1023 float4 slots
            int row = idx >> 5;             // k-row 0..31
            int c4 = idx & 31;              // float4 col
            *(float4*)&Ws[row][c4 * 4] =
                *(const float4*)(W + (size_t)(kc + row) * HID + c4 * 4);
        }
        #pragma unroll
        for (int i = 0; i < 4; i++) {
            int idx = t + i * 256;          // 0..1023
            int r = idx >> 3;               // local row 0..127
            int kq = idx & 7;               // float4 along k
            int grow = m0 + r;
            float4 v = make_float4(0.f, 0.f, 0.f, 0.f);
            if (grow < NN) v = *(const float4*)(Ain + (size_t)grow * HID + kc + kq * 4);
            Xs[kq * 4 + 0][r] = v.x;
            Xs[kq * 4 + 1][r] = v.y;
            Xs[kq * 4 + 2][r] = v.z;
            Xs[kq * 4 + 3][r] = v.w;
        }
        __syncthreads();

        #pragma unroll 4
        for (int k = 0; k < 32; k++) {
            // X pairs: rows (rb+2rp, rb+2rp+1) — direct 16B loads, no packing
            ulonglong2 xa = *(const ulonglong2*)&Xs[k][rb];
            ulonglong2 xb = *(const ulonglong2*)&Xs[k][rb + 4];
            ull x2[4] = {xa.x, xa.y, xb.x, xb.y};
            // W broadcasts: pack each scalar into both halves (ALU-pipe movs)
            float4 w0 = *(const float4*)&Ws[k][cb];
            float4 w1 = *(const float4*)&Ws[k][cb + 4];
            ull wb[8];
            wb[0] = pack2(w0.x, w0.x); wb[1] = pack2(w0.y, w0.y);
            wb[2] = pack2(w0.z, w0.z); wb[3] = pack2(w0.w, w0.w);
            wb[4] = pack2(w1.x, w1.x); wb[5] = pack2(w1.y, w1.y);
            wb[6] = pack2(w1.z, w1.z); wb[7] = pack2(w1.w, w1.w);
            #pragma unroll
            for (int rp = 0; rp < 4; rp++)
                #pragma unroll
                for (int c = 0; c < 8; c++)
                    acc2[rp][c] = fma2(x2[rp], wb[c], acc2[rp][c]);
        }
        __syncthreads();
    }

    #pragma unroll
    for (int rp = 0; rp < 4; rp++) {
        #pragma unroll
        for (int h = 0; h < 2; h++) {
            int grow = m0 + rb + rp * 2 + h;
            if (grow < NN) {
                float sc = g_dinv[grow];
                float v[8];
                #pragma unroll
                for (int c = 0; c < 8; c++) {
                    float2 p = unpack2(acc2[rp][c]);
                    v[c] = (h == 0) ? p.x : p.y;
                }
                half2 h0 = __floats2half2_rn(v[0] * sc, v[1] * sc);
                half2 h1 = __floats2half2_rn(v[2] * sc, v[3] * sc);
                half2 h2 = __floats2half2_rn(v[4] * sc, v[5] * sc);
                half2 h3 = __floats2half2_rn(v[6] * sc, v[7] * sc);
                uint4 pk;
                pk.x = *(unsigned*)&h0; pk.y = *(unsigned*)&h1;
                pk.z = *(unsigned*)&h2; pk.w = *(unsigned*)&h3;
                *(uint4*)(g_tmp + (size_t)grow * HID + cb) = pk;
            }
        }
    }
}

// ---------------- SpMM: out[d] = relu(dinv[d] * sum_{s in N(d)} g_tmp[s] + bias) ----------------
template<int DST>   // 0: write g_h1, 1: write param out
__global__ void k_spmm(const float* __restrict__ bias, float* __restrict__ outp) {
    int gw = (blockIdx.x * blockDim.x + threadIdx.x) >> 5;
    int lane = threadIdx.x & 31;
    if (gw >= NN) return;
    int start = g_rowptr[gw];
    int cnt = g_deg[gw];
    const __half* tmp = (const __half*)g_tmp;

    float4 acc = make_float4(0.f, 0.f, 0.f, 0.f);
    int j = 0;
    for (; j + 4 <= cnt; j += 4) {
        int s0 = g_col[start + j];
        int s1 = g_col[start + j + 1];
        int s2 = g_col[start + j + 2];
        int s3 = g_col[start + j + 3];
        uint2 u0 = *(const uint2*)(tmp + (size_t)s0 * HID + lane * 4);
        uint2 u1 = *(const uint2*)(tmp + (size_t)s1 * HID + lane * 4);
        uint2 u2 = *(const uint2*)(tmp + (size_t)s2 * HID + lane * 4);
        uint2 u3 = *(const uint2*)(tmp + (size_t)s3 * HID + lane * 4);
        float2 a0 = __half22float2(*(half2*)&u0.x), b0 = __half22float2(*(half2*)&u0.y);
        float2 a1 = __half22float2(*(half2*)&u1.x), b1 = __half22float2(*(half2*)&u1.y);
        float2 a2 = __half22float2(*(half2*)&u2.x), b2 = __half22float2(*(half2*)&u2.y);
        float2 a3 = __half22float2(*(half2*)&u3.x), b3 = __half22float2(*(half2*)&u3.y);
        acc.x += a0.x + a1.x + a2.x + a3.x;
        acc.y += a0.y + a1.y + a2.y + a3.y;
        acc.z += b0.x + b1.x + b2.x + b3.x;
        acc.w += b0.y + b1.y + b2.y + b3.y;
    }
    for (; j < cnt; j++) {
        int s = g_col[start + j];
        uint2 u = *(const uint2*)(tmp + (size_t)s * HID + lane * 4);
        float2 a = __half22float2(*(half2*)&u.x), b = __half22float2(*(half2*)&u.y);
        acc.x += a.x; acc.y += a.y; acc.z += b.x; acc.w += b.y;
    }

    float dv = g_dinv[gw];
    float4 b4 = *(const float4*)(bias + lane * 4);
    float4 o;
    o.x = fmaxf(fmaf(acc.x, dv, b4.x), 0.f);
    o.y = fmaxf(fmaf(acc.y, dv, b4.y), 0.f);
    o.z = fmaxf(fmaf(acc.z, dv, b4.z), 0.f);
    o.w = fmaxf(fmaf(acc.w, dv, b4.w), 0.f);
    float* dst = (DST == 0) ? (float*)g_h1 : outp;
    *(float4*)(dst + (size_t)gw * HID + lane * 4) = o;
}

// ---------------- head GEMM: S[m][c] = H[m][:] . Wh[:][c] + bh[c] ----------------
// f32x2 pairs along M: 2 row-pairs x 5 cols.
__global__ void __launch_bounds__(256)
k_gemm3(const float* __restrict__ H, const float* __restrict__ Wh,
        const float* __restrict__ bh, float* __restrict__ S) {
    __shared__ float Ws[64][40];
    __shared__ float Xs[64][132];
    int t = threadIdx.x;
    int m0 = blockIdx.x * 128;
    int tx = t & 7, ty = t >> 3;
    int rb = ty * 4, cb = tx * 5;
    ull acc2[2][5];
    #pragma unroll
    for (int rp = 0; rp < 2; rp++)
        #pragma unroll
        for (int c = 0; c < 5; c++) acc2[rp][c] = 0ULL;

    #pragma unroll
    for (int kc = 0; kc < HID; kc += 64) {
        for (int i = t; i < 64 * 40; i += 256)
            ((float*)Ws)[i] = Wh[(size_t)(kc + (i / 40)) * NCLS + (i % 40)];
        #pragma unroll
        for (int i = 0; i < 8; i++) {
            int idx = t + i * 256;
            int r = idx >> 4;               // local row 0..127
            int kq = idx & 15;              // float4 along k
            int grow = m0 + r;
            float4 v = make_float4(0.f, 0.f, 0.f, 0.f);
            if (grow < NN) v = *(const float4*)(H + (size_t)grow * HID + kc + kq * 4);
            Xs[kq * 4 + 0][r] = v.x;
            Xs[kq * 4 + 1][r] = v.y;
            Xs[kq * 4 + 2][r] = v.z;
            Xs[kq * 4 + 3][r] = v.w;
        }
        __syncthreads();

        #pragma unroll 8
        for (int k = 0; k < 64; k++) {
            ulonglong2 xa = *(const ulonglong2*)&Xs[k][rb];
            ull x2[2] = {xa.x, xa.y};
            ull wb[5];
            #pragma unroll
            for (int c = 0; c < 5; c++) {
                float w = Ws[k][cb + c];
                wb[c] = pack2(w, w);
            }
            #pragma unroll
            for (int rp = 0; rp < 2; rp++)
                #pragma unroll
                for (int c = 0; c < 5; c++)
                    acc2[rp][c] = fma2(x2[rp], wb[c], acc2[rp][c]);
        }
        __syncthreads();
    }

    #pragma unroll
    for (int rp = 0; rp < 2; rp++) {
        #pragma unroll
        for (int h = 0; h < 2; h++) {
            int grow = m0 + rb + rp * 2 + h;
            if (grow < NN) {
                #pragma unroll
                for (int c = 0; c < 5; c++) {
                    float2 p = unpack2(acc2[rp][c]);
                    float v = (h == 0) ? p.x : p.y;
                    S[(size_t)grow * NCLS + cb + c] = v + bh[cb + c];
                }
            }
        }
    }
}

// ---------------- launch ----------------
extern "C" void kernel_launch(void* const* d_in, const int* in_sizes, int n_in,
                              void* d_out, int out_size) {
    const float* x   = (const float*)d_in[0];
    const void*  ei  = d_in[1];                 // int32 or int64, detected on device
    const float* W1  = (const float*)d_in[2];
    const float* b1  = (const float*)d_in[3];
    const float* W2  = (const float*)d_in[4];
    const float* b2  = (const float*)d_in[5];
    const float* Wh  = (const float*)d_in[6];
    const float* bh  = (const float*)d_in[7];

    float* out = (float*)d_out;
    float* scores = out;                       // [NN, 40]
    float* h2 = out + (size_t)NN * NCLS;       // [NN, 128]

    const int TB = 256;
    k_init_deg<<<(NN + TB - 1) / TB, TB>>>((const int*)ei);
    k_count<<<(EE + TB - 1) / TB, TB>>>(ei);
    k_scan1<<<NB, TB>>>();
    k_scan2<<<1, 512>>>();
    k_scan3<<<NB, TB>>>();
    k_selfloop<<<(NN + TB - 1) / TB, TB>>>();
    k_fill<<<(EE + TB - 1) / TB, TB>>>(ei);

    int gemm_grid = (NN + 127) / 128;
    int spmm_grid = (NN * 32 + TB - 1) / TB;

    // layer 1
    k_gemm<0><<<gemm_grid, TB>>>(x, W1);
    k_spmm<0><<<spmm_grid, TB>>>(b1, nullptr);
    // layer 2 (h2 written straight into output buffer)
    k_gemm<1><<<gemm_grid, TB>>>(x, W2);
    k_spmm<1><<<spmm_grid, TB>>>(b2, h2);
    // head
    k_gemm3<<<gemm_grid, TB>>>(h2, Wh, bh, scores);
}

// round 10
// speedup vs baseline: 1.4006x; 1.4006x over previous
#include <cuda_runtime.h>
#include <cuda_fp16.h>
#include <cstdint>

// Problem constants
#define NN 100000
#define EE 1600000
#define HID 128
#define NCLS 40
#define NB 391              // ceil(NN/256)

typedef unsigned long long ull;

__device__ __forceinline__ ull fma2(ull a, ull b, ull c) {
    ull d;
    asm("fma.rn.f32x2 %0, %1, %2, %3;" : "=l"(d) : "l"(a), "l"(b), "l"(c));
    return d;
}
__device__ __forceinline__ ull pack2(float lo, float hi) {
    ull d;
    asm("mov.b64 %0, {%1, %2};" : "=l"(d) : "f"(lo), "f"(hi));
    return d;
}
__device__ __forceinline__ float2 unpack2(ull v) {
    float lo, hi;
    asm("mov.b64 {%0, %1}, %2;" : "=f"(lo), "=f"(hi) : "l"(v));
    return make_float2(lo, hi);
}

// ---------------- mma.sync helpers ----------------
__device__ __forceinline__ void ldsm_x4(uint32_t addr, uint32_t& r0, uint32_t& r1,
                                        uint32_t& r2, uint32_t& r3) {
    asm volatile("ldmatrix.sync.aligned.m8n8.x4.shared.b16 {%0,%1,%2,%3}, [%4];"
                 : "=r"(r0), "=r"(r1), "=r"(r2), "=r"(r3) : "r"(addr));
}
__device__ __forceinline__ void ldsm_x4_t(uint32_t addr, uint32_t& r0, uint32_t& r1,
                                          uint32_t& r2, uint32_t& r3) {
    asm volatile("ldmatrix.sync.aligned.m8n8.x4.trans.shared.b16 {%0,%1,%2,%3}, [%4];"
                 : "=r"(r0), "=r"(r1), "=r"(r2), "=r"(r3) : "r"(addr));
}
__device__ __forceinline__ void mma16816(float c[4], const uint32_t a[4],
                                         uint32_t b0, uint32_t b1) {
    asm volatile(
        "mma.sync.aligned.m16n8k16.row.col.f32.f16.f16.f32 "
        "{%0,%1,%2,%3}, {%4,%5,%6,%7}, {%8,%9}, {%0,%1,%2,%3};"
        : "+f"(c[0]), "+f"(c[1]), "+f"(c[2]), "+f"(c[3])
        : "r"(a[0]), "r"(a[1]), "r"(a[2]), "r"(a[3]), "r"(b0), "r"(b1));
}

// ---------------- device scratch (static; no cudaMalloc allowed) ----------------
__device__ __half g_tmp[(size_t)NN * HID];  // fp16 messages (pre-scaled by dinv[src])
__device__ float  g_h1[(size_t)NN * HID];   // layer-1 hidden (fp32)
__device__ float  g_dinv[NN];
__device__ int    g_deg[NN];                // in-degree incl self loop
__device__ int    g_rowptr[NN + 1];
__device__ int    g_cursor[NN];
__device__ int    g_col[EE + NN];
__device__ int    g_bsum[512];
__device__ int    g_fmt;                    // 1 = edge_index is int64, 0 = int32

// ---------------- CSR build ----------------
__global__ void k_init_deg(const int* __restrict__ ei) {
    int i = blockIdx.x * blockDim.x + threadIdx.x;
    if (i < NN) g_deg[i] = 1;   // self loop
    if (i == 0) {
        int is64 = 1;
        #pragma unroll
        for (int j = 1; j < 64; j += 2) is64 &= (ei[j] == 0);
        g_fmt = is64;
    }
}

__device__ __forceinline__ int edge_at(const void* __restrict__ ei, size_t idx) {
    if (g_fmt) return (int)((const long long*)ei)[idx];
    return ((const int*)ei)[idx];
}

__global__ void k_count(const void* __restrict__ ei) {
    int e = blockIdx.x * blockDim.x + threadIdx.x;
    if (e < EE) {
        int d = edge_at(ei, (size_t)EE + e);
        if ((unsigned)d < NN) atomicAdd(&g_deg[d], 1);
    }
}

__global__ void k_scan1() {
    __shared__ int s[256];
    int b = blockIdx.x, t = threadIdx.x;
    int i = b * 256 + t;
    int v = (i < NN) ? g_deg[i] : 0;
    s[t] = v;
    __syncthreads();
    #pragma unroll
    for (int off = 1; off < 256; off <<= 1) {
        int add = (t >= off) ? s[t - off] : 0;
        __syncthreads();
        s[t] += add;
        __syncthreads();
    }
    if (i < NN) g_rowptr[i] = s[t] - v;
    if (t == 255) g_bsum[b] = s[255];
}

__global__ void k_scan2() {
    __shared__ int s[512];
    int t = threadIdx.x;
    int v = (t < NB) ? g_bsum[t] : 0;
    s[t] = v;
    __syncthreads();
    #pragma unroll
    for (int off = 1; off < 512; off <<= 1) {
        int add = (t >= off) ? s[t - off] : 0;
        __syncthreads();
        s[t] += add;
        __syncthreads();
    }
    if (t < NB) g_bsum[t] = s[t] - v;
}

__global__ void k_scan3() {
    int b = blockIdx.x, t = threadIdx.x;
    int i = b * 256 + t;
    if (i < NN) g_rowptr[i] += g_bsum[b];
    if (i == 0) g_rowptr[NN] = EE + NN;
}

__global__ void k_selfloop() {
    int i = blockIdx.x * blockDim.x + threadIdx.x;
    if (i < NN) {
        int rp = g_rowptr[i];
        if ((unsigned)rp < (unsigned)(EE + NN)) g_col[rp] = i;
        g_cursor[i] = 1;
        g_dinv[i] = rsqrtf((float)g_deg[i]);
    }
}

__global__ void k_fill(const void* __restrict__ ei) {
    int e = blockIdx.x * blockDim.x + threadIdx.x;
    if (e < EE) {
        int s = edge_at(ei, e);
        int d = edge_at(ei, (size_t)EE + e);
        if ((unsigned)d < NN) {
            int pos = atomicAdd(&g_cursor[d], 1);
            int w = g_rowptr[d] + pos;
            int c = ((unsigned)s < NN) ? s : d;
            if ((unsigned)w < (unsigned)(EE + NN)) g_col[w] = c;
        }
    }
}

// ---------------- tensor-core GEMM: g_tmp[m][n] = half((A.W)[m][n] * dinv[m]) ----------------
// BM=128, BN=128, BK=32, fp16 operands, fp32 accumulate via mma.sync.m16n8k16.
// 8 warps: warp_m = wid&3 (32 rows), warp_n = wid>>2 (64 cols).
template<int SRC>   // 0: read A param, 1: read g_h1
__global__ void __launch_bounds__(256, 2)
k_gemm(const float* __restrict__ A, const float* __restrict__ W) {
    __shared__ __half As[128][40];   // pad: row stride 80B -> ldmatrix conflict-free
    __shared__ __half Wsh[32][136];  // pad: row stride 272B -> conflict-free
    const float* Ain = (SRC == 0) ? A : (const float*)g_h1;
    int t = threadIdx.x, lane = t & 31, wid = t >> 5;
    int m0 = blockIdx.x * 128;
    int wm = (wid & 3) * 32;
    int wn = (wid >> 2) * 64;

    float acc[2][8][4];
    #pragma unroll
    for (int mt = 0; mt < 2; mt++)
        #pragma unroll
        for (int nt = 0; nt < 8; nt++)
            #pragma unroll
            for (int q = 0; q < 4; q++) acc[mt][nt][q] = 0.f;

    // precompute ldmatrix smem addresses (lane-dependent parts)
    uint32_t as_base = (uint32_t)__cvta_generic_to_shared(&As[0][0]);
    uint32_t ws_base = (uint32_t)__cvta_generic_to_shared(&Wsh[0][0]);
    int a_row = wm + (lane & 15);          // + mt*16
    int a_col = (lane >> 4) * 8;           // + ks
    int g = lane >> 3;
    int b_krow = (lane & 7) + (g >> 1) * 8;   // + ks
    int b_ncol = wn + (g & 1) * 8;            // + ntq*16

    #pragma unroll
    for (int kc = 0; kc < HID; kc += 32) {
        // stage A chunk [128][32] fp32->fp16
        {
            int r = t >> 1, cs = (t & 1) * 16;
            int grow = m0 + r;
            float4 v0, v1, v2, v3;
            if (grow < NN) {
                const float4* src = (const float4*)(Ain + (size_t)grow * HID + kc + cs);
                v0 = src[0]; v1 = src[1]; v2 = src[2]; v3 = src[3];
            } else {
                v0 = v1 = v2 = v3 = make_float4(0.f, 0.f, 0.f, 0.f);
            }
            half2 h0 = __floats2half2_rn(v0.x, v0.y), h1 = __floats2half2_rn(v0.z, v0.w);
            half2 h2 = __floats2half2_rn(v1.x, v1.y), h3 = __floats2half2_rn(v1.z, v1.w);
            half2 h4 = __floats2half2_rn(v2.x, v2.y), h5 = __floats2half2_rn(v2.z, v2.w);
            half2 h6 = __floats2half2_rn(v3.x, v3.y), h7 = __floats2half2_rn(v3.z, v3.w);
            uint4 p0, p1;
            p0.x = *(unsigned*)&h0; p0.y = *(unsigned*)&h1;
            p0.z = *(unsigned*)&h2; p0.w = *(unsigned*)&h3;
            p1.x = *(unsigned*)&h4; p1.y = *(unsigned*)&h5;
            p1.z = *(unsigned*)&h6; p1.w = *(unsigned*)&h7;
            *(uint4*)&As[r][cs] = p0;
            *(uint4*)&As[r][cs + 8] = p1;
        }
        // stage W chunk [32][128] fp32->fp16
        {
            int r = t >> 3, cs = (t & 7) * 16;
            const float4* src = (const float4*)(W + (size_t)(kc + r) * HID + cs);
            float4 v0 = src[0], v1 = src[1], v2 = src[2], v3 = src[3];
            half2 h0 = __floats2half2_rn(v0.x, v0.y), h1 = __floats2half2_rn(v0.z, v0.w);
            half2 h2 = __floats2half2_rn(v1.x, v1.y), h3 = __floats2half2_rn(v1.z, v1.w);
            half2 h4 = __floats2half2_rn(v2.x, v2.y), h5 = __floats2half2_rn(v2.z, v2.w);
            half2 h6 = __floats2half2_rn(v3.x, v3.y), h7 = __floats2half2_rn(v3.z, v3.w);
            uint4 p0, p1;
            p0.x = *(unsigned*)&h0; p0.y = *(unsigned*)&h1;
            p0.z = *(unsigned*)&h2; p0.w = *(unsigned*)&h3;
            p1.x = *(unsigned*)&h4; p1.y = *(unsigned*)&h5;
            p1.z = *(unsigned*)&h6; p1.w = *(unsigned*)&h7;
            *(uint4*)&Wsh[r][cs] = p0;
            *(uint4*)&Wsh[r][cs + 8] = p1;
        }
        __syncthreads();

        #pragma unroll
        for (int ks = 0; ks < 32; ks += 16) {
            uint32_t a[2][4];
            #pragma unroll
            for (int mt = 0; mt < 2; mt++) {
                uint32_t addr = as_base +
                    ((a_row + mt * 16) * 40 + ks + a_col) * 2;
                ldsm_x4(addr, a[mt][0], a[mt][1], a[mt][2], a[mt][3]);
            }
            uint32_t b[8][2];
            #pragma unroll
            for (int ntq = 0; ntq < 4; ntq++) {
                uint32_t addr = ws_base +
                    ((ks + b_krow) * 136 + b_ncol + ntq * 16) * 2;
                uint32_t r0, r1, r2, r3;
                ldsm_x4_t(addr, r0, r1, r2, r3);
                b[ntq * 2][0] = r0; b[ntq * 2 + 1][0] = r1;
                b[ntq * 2][1] = r2; b[ntq * 2 + 1][1] = r3;
            }
            #pragma unroll
            for (int mt = 0; mt < 2; mt++)
                #pragma unroll
                for (int nt = 0; nt < 8; nt++)
                    mma16816(acc[mt][nt], a[mt], b[nt][0], b[nt][1]);
        }
        __syncthreads();
    }

    // epilogue: scale by dinv[row], convert to fp16, store
    int qr = lane >> 2, qc = (lane & 3) * 2;
    #pragma unroll
    for (int mt = 0; mt < 2; mt++) {
        int row_lo = m0 + wm + mt * 16 + qr;
        int row_hi = row_lo + 8;
        float sc_lo = (row_lo < NN) ? g_dinv[row_lo] : 0.f;
        float sc_hi = (row_hi < NN) ? g_dinv[row_hi] : 0.f;
        #pragma unroll
        for (int nt = 0; nt < 8; nt++) {
            int colg = wn + nt * 8 + qc;
            if (row_lo < NN) {
                half2 h = __floats2half2_rn(acc[mt][nt][0] * sc_lo, acc[mt][nt][1] * sc_lo);
                *(half2*)(g_tmp + (size_t)row_lo * HID + colg) = h;
            }
            if (row_hi < NN) {
                half2 h = __floats2half2_rn(acc[mt][nt][2] * sc_hi, acc[mt][nt][3] * sc_hi);
                *(half2*)(g_tmp + (size_t)row_hi * HID + colg) = h;
            }
        }
    }
}

// ---------------- SpMM: out[d] = relu(dinv[d] * sum_{s in N(d)} g_tmp[s] + bias) ----------------
template<int DST>   // 0: write g_h1, 1: write param out
__global__ void k_spmm(const float* __restrict__ bias, float* __restrict__ outp) {
    int gw = (blockIdx.x * blockDim.x + threadIdx.x) >> 5;
    int lane = threadIdx.x & 31;
    if (gw >= NN) return;
    int start = g_rowptr[gw];
    int cnt = g_deg[gw];
    const __half* tmp = (const __half*)g_tmp;

    float4 acc = make_float4(0.f, 0.f, 0.f, 0.f);
    int j = 0;
    for (; j + 4 <= cnt; j += 4) {
        int s0 = g_col[start + j];
        int s1 = g_col[start + j + 1];
        int s2 = g_col[start + j + 2];
        int s3 = g_col[start + j + 3];
        uint2 u0 = *(const uint2*)(tmp + (size_t)s0 * HID + lane * 4);
        uint2 u1 = *(const uint2*)(tmp + (size_t)s1 * HID + lane * 4);
        uint2 u2 = *(const uint2*)(tmp + (size_t)s2 * HID + lane * 4);
        uint2 u3 = *(const uint2*)(tmp + (size_t)s3 * HID + lane * 4);
        float2 a0 = __half22float2(*(half2*)&u0.x), b0 = __half22float2(*(half2*)&u0.y);
        float2 a1 = __half22float2(*(half2*)&u1.x), b1 = __half22float2(*(half2*)&u1.y);
        float2 a2 = __half22float2(*(half2*)&u2.x), b2 = __half22float2(*(half2*)&u2.y);
        float2 a3 = __half22float2(*(half2*)&u3.x), b3 = __half22float2(*(half2*)&u3.y);
        acc.x += a0.x + a1.x + a2.x + a3.x;
        acc.y += a0.y + a1.y + a2.y + a3.y;
        acc.z += b0.x + b1.x + b2.x + b3.x;
        acc.w += b0.y + b1.y + b2.y + b3.y;
    }
    for (; j < cnt; j++) {
        int s = g_col[start + j];
        uint2 u = *(const uint2*)(tmp + (size_t)s * HID + lane * 4);
        float2 a = __half22float2(*(half2*)&u.x), b = __half22float2(*(half2*)&u.y);
        acc.x += a.x; acc.y += a.y; acc.z += b.x; acc.w += b.y;
    }

    float dv = g_dinv[gw];
    float4 b4 = *(const float4*)(bias + lane * 4);
    float4 o;
    o.x = fmaxf(fmaf(acc.x, dv, b4.x), 0.f);
    o.y = fmaxf(fmaf(acc.y, dv, b4.y), 0.f);
    o.z = fmaxf(fmaf(acc.z, dv, b4.z), 0.f);
    o.w = fmaxf(fmaf(acc.w, dv, b4.w), 0.f);
    float* dst = (DST == 0) ? (float*)g_h1 : outp;
    *(float4*)(dst + (size_t)gw * HID + lane * 4) = o;
}

// ---------------- head GEMM: S[m][c] = H[m][:] . Wh[:][c] + bh[c] ----------------
__global__ void __launch_bounds__(256)
k_gemm3(const float* __restrict__ H, const float* __restrict__ Wh,
        const float* __restrict__ bh, float* __restrict__ S) {
    __shared__ float Ws[64][40];
    __shared__ float Xs[64][132];
    int t = threadIdx.x;
    int m0 = blockIdx.x * 128;
    int tx = t & 7, ty = t >> 3;
    int rb = ty * 4, cb = tx * 5;
    ull acc2[2][5];
    #pragma unroll
    for (int rp = 0; rp < 2; rp++)
        #pragma unroll
        for (int c = 0; c < 5; c++) acc2[rp][c] = 0ULL;

    #pragma unroll
    for (int kc = 0; kc < HID; kc += 64) {
        for (int i = t; i < 64 * 40; i += 256)
            ((float*)Ws)[i] = Wh[(size_t)(kc + (i / 40)) * NCLS + (i % 40)];
        #pragma unroll
        for (int i = 0; i < 8; i++) {
            int idx = t + i * 256;
            int r = idx >> 4;
            int kq = idx & 15;
            int grow = m0 + r;
            float4 v = make_float4(0.f, 0.f, 0.f, 0.f);
            if (grow < NN) v = *(const float4*)(H + (size_t)grow * HID + kc + kq * 4);
            Xs[kq * 4 + 0][r] = v.x;
            Xs[kq * 4 + 1][r] = v.y;
            Xs[kq * 4 + 2][r] = v.z;
            Xs[kq * 4 + 3][r] = v.w;
        }
        __syncthreads();

        #pragma unroll 8
        for (int k = 0; k < 64; k++) {
            ulonglong2 xa = *(const ulonglong2*)&Xs[k][rb];
            ull x2[2] = {xa.x, xa.y};
            ull wb[5];
            #pragma unroll
            for (int c = 0; c < 5; c++) {
                float w = Ws[k][cb + c];
                wb[c] = pack2(w, w);
            }
            #pragma unroll
            for (int rp = 0; rp < 2; rp++)
                #pragma unroll
                for (int c = 0; c < 5; c++)
                    acc2[rp][c] = fma2(x2[rp], wb[c], acc2[rp][c]);
        }
        __syncthreads();
    }

    #pragma unroll
    for (int rp = 0; rp < 2; rp++) {
        #pragma unroll
        for (int h = 0; h < 2; h++) {
            int grow = m0 + rb + rp * 2 + h;
            if (grow < NN) {
                #pragma unroll
                for (int c = 0; c < 5; c++) {
                    float2 p = unpack2(acc2[rp][c]);
                    float v = (h == 0) ? p.x : p.y;
                    S[(size_t)grow * NCLS + cb + c] = v + bh[cb + c];
                }
            }
        }
    }
}

// ---------------- launch ----------------
extern "C" void kernel_launch(void* const* d_in, const int* in_sizes, int n_in,
                              void* d_out, int out_size) {
    const float* x   = (const float*)d_in[0];
    const void*  ei  = d_in[1];                 // int32 or int64, detected on device
    const float* W1  = (const float*)d_in[2];
    const float* b1  = (const float*)d_in[3];
    const float* W2  = (const float*)d_in[4];
    const float* b2  = (const float*)d_in[5];
    const float* Wh  = (const float*)d_in[6];
    const float* bh  = (const float*)d_in[7];

    float* out = (float*)d_out;
    float* scores = out;                       // [NN, 40]
    float* h2 = out + (size_t)NN * NCLS;       // [NN, 128]

    const int TB = 256;
    k_init_deg<<<(NN + TB - 1) / TB, TB>>>((const int*)ei);
    k_count<<<(EE + TB - 1) / TB, TB>>>(ei);
    k_scan1<<<NB, TB>>>();
    k_scan2<<<1, 512>>>();
    k_scan3<<<NB, TB>>>();
    k_selfloop<<<(NN + TB - 1) / TB, TB>>>();
    k_fill<<<(EE + TB - 1) / TB, TB>>>(ei);

    int gemm_grid = (NN + 127) / 128;
    int spmm_grid = (NN * 32 + TB - 1) / TB;

    // layer 1
    k_gemm<0><<<gemm_grid, TB>>>(x, W1);
    k_spmm<0><<<spmm_grid, TB>>>(b1, nullptr);
    // layer 2 (h2 written straight into output buffer)
    k_gemm<1><<<gemm_grid, TB>>>(x, W2);
    k_spmm<1><<<spmm_grid, TB>>>(b2, h2);
    // head
    k_gemm3<<<gemm_grid, TB>>>(h2, Wh, bh, scores);
}

// round 11
// speedup vs baseline: 1.6101x; 1.1495x over previous
#include <cuda_runtime.h>
#include <cuda_fp16.h>
#include <cstdint>

// Problem constants
#define NN 100000
#define EE 1600000
#define HID 128
#define NCLS 40
#define NB 391              // ceil(NN/256)

// ---------------- mma.sync helpers ----------------
__device__ __forceinline__ void ldsm_x4(uint32_t addr, uint32_t& r0, uint32_t& r1,
                                        uint32_t& r2, uint32_t& r3) {
    asm volatile("ldmatrix.sync.aligned.m8n8.x4.shared.b16 {%0,%1,%2,%3}, [%4];"
                 : "=r"(r0), "=r"(r1), "=r"(r2), "=r"(r3) : "r"(addr));
}
__device__ __forceinline__ void ldsm_x4_t(uint32_t addr, uint32_t& r0, uint32_t& r1,
                                          uint32_t& r2, uint32_t& r3) {
    asm volatile("ldmatrix.sync.aligned.m8n8.x4.trans.shared.b16 {%0,%1,%2,%3}, [%4];"
                 : "=r"(r0), "=r"(r1), "=r"(r2), "=r"(r3) : "r"(addr));
}
__device__ __forceinline__ void mma16816(float c[4], const uint32_t a[4],
                                         uint32_t b0, uint32_t b1) {
    asm volatile(
        "mma.sync.aligned.m16n8k16.row.col.f32.f16.f16.f32 "
        "{%0,%1,%2,%3}, {%4,%5,%6,%7}, {%8,%9}, {%0,%1,%2,%3};"
        : "+f"(c[0]), "+f"(c[1]), "+f"(c[2]), "+f"(c[3])
        : "r"(a[0]), "r"(a[1]), "r"(a[2]), "r"(a[3]), "r"(b0), "r"(b1));
}

// ---------------- device scratch (static; no cudaMalloc allowed) ----------------
__device__ __half g_tmp[(size_t)NN * HID];  // fp16 messages (pre-scaled by dinv[src])
__device__ __half g_h1h[(size_t)NN * HID];  // layer-1 hidden, fp16
__device__ __half g_h2h[(size_t)NN * HID];  // layer-2 hidden, fp16 (head input)
__device__ float  g_dinv[NN];
__device__ int    g_deg[NN];                // in-degree incl self loop
__device__ int    g_rowptr[NN + 1];
__device__ int    g_cursor[NN];
__device__ int    g_col[EE + NN];
__device__ int    g_bsum[512];
__device__ int    g_fmt;                    // 1 = edge_index is int64, 0 = int32

// ---------------- CSR build ----------------
__global__ void k_init_deg(const int* __restrict__ ei) {
    int i = blockIdx.x * blockDim.x + threadIdx.x;
    if (i < NN) g_deg[i] = 1;   // self loop
    if (i == 0) {
        int is64 = 1;
        #pragma unroll
        for (int j = 1; j < 64; j += 2) is64 &= (ei[j] == 0);
        g_fmt = is64;
    }
}

__device__ __forceinline__ int edge_at(const void* __restrict__ ei, size_t idx) {
    if (g_fmt) return (int)((const long long*)ei)[idx];
    return ((const int*)ei)[idx];
}

__global__ void k_count(const void* __restrict__ ei) {
    int e = blockIdx.x * blockDim.x + threadIdx.x;
    if (e < EE) {
        int d = edge_at(ei, (size_t)EE + e);
        if ((unsigned)d < NN) atomicAdd(&g_deg[d], 1);
    }
}

__global__ void k_dinv() {
    int i = blockIdx.x * blockDim.x + threadIdx.x;
    if (i < NN) g_dinv[i] = rsqrtf((float)g_deg[i]);
}

__global__ void k_scan1() {
    __shared__ int s[256];
    int b = blockIdx.x, t = threadIdx.x;
    int i = b * 256 + t;
    int v = (i < NN) ? g_deg[i] : 0;
    s[t] = v;
    __syncthreads();
    #pragma unroll
    for (int off = 1; off < 256; off <<= 1) {
        int add = (t >= off) ? s[t - off] : 0;
        __syncthreads();
        s[t] += add;
        __syncthreads();
    }
    if (i < NN) g_rowptr[i] = s[t] - v;
    if (t == 255) g_bsum[b] = s[255];
}

__global__ void k_scan2() {
    __shared__ int s[512];
    int t = threadIdx.x;
    int v = (t < NB) ? g_bsum[t] : 0;
    s[t] = v;
    __syncthreads();
    #pragma unroll
    for (int off = 1; off < 512; off <<= 1) {
        int add = (t >= off) ? s[t - off] : 0;
        __syncthreads();
        s[t] += add;
        __syncthreads();
    }
    if (t < NB) g_bsum[t] = s[t] - v;
}

// scan3 + selfloop fused
__global__ void k_scan3() {
    int b = blockIdx.x, t = threadIdx.x;
    int i = b * 256 + t;
    if (i < NN) {
        int rp = g_rowptr[i] + g_bsum[b];
        g_rowptr[i] = rp;
        if ((unsigned)rp < (unsigned)(EE + NN)) g_col[rp] = i;   // self loop at slot 0
        g_cursor[i] = 1;
    }
    if (i == 0) g_rowptr[NN] = EE + NN;
}

__global__ void k_fill(const void* __restrict__ ei) {
    int e = blockIdx.x * blockDim.x + threadIdx.x;
    if (e < EE) {
        int s = edge_at(ei, e);
        int d = edge_at(ei, (size_t)EE + e);
        if ((unsigned)d < NN) {
            int pos = atomicAdd(&g_cursor[d], 1);
            int w = g_rowptr[d] + pos;
            int c = ((unsigned)s < NN) ? s : d;
            if ((unsigned)w < (unsigned)(EE + NN)) g_col[w] = c;
        }
    }
}

// ---------------- tensor-core GEMM: g_tmp[m][n] = half((A.W)[m][n] * dinv[m]) ----------------
// BM=128, BN=128, BK=32, fp16 operands, fp32 accumulate via mma.sync.m16n8k16.
// 8 warps: warp_m = wid&3 (32 rows), warp_n = wid>>2 (64 cols).
template<int SRC>   // 0: read fp32 A param, 1: read fp16 g_h1h
__global__ void __launch_bounds__(256, 2)
k_gemm(const float* __restrict__ A, const float* __restrict__ W) {
    __shared__ __align__(16) __half As[128][40];   // 80B row stride: ldmatrix ~conflict-free
    __shared__ __align__(16) __half Wsh[32][136];  // 272B row stride
    int t = threadIdx.x, lane = t & 31, wid = t >> 5;
    int m0 = blockIdx.x * 128;
    int wm = (wid & 3) * 32;
    int wn = (wid >> 2) * 64;

    float acc[2][8][4];
    #pragma unroll
    for (int mt = 0; mt < 2; mt++)
        #pragma unroll
        for (int nt = 0; nt < 8; nt++)
            #pragma unroll
            for (int q = 0; q < 4; q++) acc[mt][nt][q] = 0.f;

    uint32_t as_base = (uint32_t)__cvta_generic_to_shared(&As[0][0]);
    uint32_t ws_base = (uint32_t)__cvta_generic_to_shared(&Wsh[0][0]);
    int a_row = wm + (lane & 15);
    int a_col = (lane >> 4) * 8;
    int g = lane >> 3;
    int b_krow = (lane & 7) + (g >> 1) * 8;
    int b_ncol = wn + (g & 1) * 8;

    #pragma unroll
    for (int kc = 0; kc < HID; kc += 32) {
        // stage A chunk [128][32]
        if (SRC == 0) {
            int r = t >> 1, cs = (t & 1) * 16;
            int grow = m0 + r;
            float4 v0, v1, v2, v3;
            if (grow < NN) {
                const float4* src = (const float4*)(A + (size_t)grow * HID + kc + cs);
                v0 = src[0]; v1 = src[1]; v2 = src[2]; v3 = src[3];
            } else {
                v0 = v1 = v2 = v3 = make_float4(0.f, 0.f, 0.f, 0.f);
            }
            half2 h0 = __floats2half2_rn(v0.x, v0.y), h1 = __floats2half2_rn(v0.z, v0.w);
            half2 h2 = __floats2half2_rn(v1.x, v1.y), h3 = __floats2half2_rn(v1.z, v1.w);
            half2 h4 = __floats2half2_rn(v2.x, v2.y), h5 = __floats2half2_rn(v2.z, v2.w);
            half2 h6 = __floats2half2_rn(v3.x, v3.y), h7 = __floats2half2_rn(v3.z, v3.w);
            uint4 p0, p1;
            p0.x = *(unsigned*)&h0; p0.y = *(unsigned*)&h1;
            p0.z = *(unsigned*)&h2; p0.w = *(unsigned*)&h3;
            p1.x = *(unsigned*)&h4; p1.y = *(unsigned*)&h5;
            p1.z = *(unsigned*)&h6; p1.w = *(unsigned*)&h7;
            *(uint4*)&As[r][cs] = p0;
            *(uint4*)&As[r][cs + 8] = p1;
        } else {
            int r = t >> 1, cs = (t & 1) * 16;
            int grow = m0 + r;
            uint4 p0 = make_uint4(0, 0, 0, 0), p1 = make_uint4(0, 0, 0, 0);
            if (grow < NN) {
                const uint4* src = (const uint4*)(g_h1h + (size_t)grow * HID + kc + cs);
                p0 = src[0]; p1 = src[1];
            }
            *(uint4*)&As[r][cs] = p0;
            *(uint4*)&As[r][cs + 8] = p1;
        }
        // stage W chunk [32][128] fp32->fp16
        {
            int r = t >> 3, cs = (t & 7) * 16;
            const float4* src = (const float4*)(W + (size_t)(kc + r) * HID + cs);
            float4 v0 = src[0], v1 = src[1], v2 = src[2], v3 = src[3];
            half2 h0 = __floats2half2_rn(v0.x, v0.y), h1 = __floats2half2_rn(v0.z, v0.w);
            half2 h2 = __floats2half2_rn(v1.x, v1.y), h3 = __floats2half2_rn(v1.z, v1.w);
            half2 h4 = __floats2half2_rn(v2.x, v2.y), h5 = __floats2half2_rn(v2.z, v2.w);
            half2 h6 = __floats2half2_rn(v3.x, v3.y), h7 = __floats2half2_rn(v3.z, v3.w);
            uint4 p0, p1;
            p0.x = *(unsigned*)&h0; p0.y = *(unsigned*)&h1;
            p0.z = *(unsigned*)&h2; p0.w = *(unsigned*)&h3;
            p1.x = *(unsigned*)&h4; p1.y = *(unsigned*)&h5;
            p1.z = *(unsigned*)&h6; p1.w = *(unsigned*)&h7;
            *(uint4*)&Wsh[r][cs] = p0;
            *(uint4*)&Wsh[r][cs + 8] = p1;
        }
        __syncthreads();

        #pragma unroll
        for (int ks = 0; ks < 32; ks += 16) {
            uint32_t a[2][4];
            #pragma unroll
            for (int mt = 0; mt < 2; mt++) {
                uint32_t addr = as_base + ((a_row + mt * 16) * 40 + ks + a_col) * 2;
                ldsm_x4(addr, a[mt][0], a[mt][1], a[mt][2], a[mt][3]);
            }
            uint32_t b[8][2];
            #pragma unroll
            for (int ntq = 0; ntq < 4; ntq++) {
                uint32_t addr = ws_base + ((ks + b_krow) * 136 + b_ncol + ntq * 16) * 2;
                uint32_t r0, r1, r2, r3;
                ldsm_x4_t(addr, r0, r1, r2, r3);
                b[ntq * 2][0] = r0; b[ntq * 2 + 1][0] = r1;
                b[ntq * 2][1] = r2; b[ntq * 2 + 1][1] = r3;
            }
            #pragma unroll
            for (int mt = 0; mt < 2; mt++)
                #pragma unroll
                for (int nt = 0; nt < 8; nt++)
                    mma16816(acc[mt][nt], a[mt], b[nt][0], b[nt][1]);
        }
        __syncthreads();
    }

    // epilogue: scale by dinv[row], convert to fp16, store
    int qr = lane >> 2, qc = (lane & 3) * 2;
    #pragma unroll
    for (int mt = 0; mt < 2; mt++) {
        int row_lo = m0 + wm + mt * 16 + qr;
        int row_hi = row_lo + 8;
        float sc_lo = (row_lo < NN) ? g_dinv[row_lo] : 0.f;
        float sc_hi = (row_hi < NN) ? g_dinv[row_hi] : 0.f;
        #pragma unroll
        for (int nt = 0; nt < 8; nt++) {
            int colg = wn + nt * 8 + qc;
            if (row_lo < NN) {
                half2 h = __floats2half2_rn(acc[mt][nt][0] * sc_lo, acc[mt][nt][1] * sc_lo);
                *(half2*)(g_tmp + (size_t)row_lo * HID + colg) = h;
            }
            if (row_hi < NN) {
                half2 h = __floats2half2_rn(acc[mt][nt][2] * sc_hi, acc[mt][nt][3] * sc_hi);
                *(half2*)(g_tmp + (size_t)row_hi * HID + colg) = h;
            }
        }
    }
}

// ---------------- SpMM: out[d] = relu(dinv[d] * sum_{s in N(d)} g_tmp[s] + bias) ----------------
// DST=0: write fp16 g_h1h only. DST=1: write fp32 outp (h2) + fp16 g_h2h.
template<int DST>
__global__ void k_spmm(const float* __restrict__ bias, float* __restrict__ outp) {
    int gw = (blockIdx.x * blockDim.x + threadIdx.x) >> 5;
    int lane = threadIdx.x & 31;
    if (gw >= NN) return;
    int start = g_rowptr[gw];
    int cnt = g_deg[gw];
    const __half* tmp = (const __half*)g_tmp;

    float4 acc = make_float4(0.f, 0.f, 0.f, 0.f);
    int j = 0;
    for (; j + 4 <= cnt; j += 4) {
        int s0 = g_col[start + j];
        int s1 = g_col[start + j + 1];
        int s2 = g_col[start + j + 2];
        int s3 = g_col[start + j + 3];
        uint2 u0 = *(const uint2*)(tmp + (size_t)s0 * HID + lane * 4);
        uint2 u1 = *(const uint2*)(tmp + (size_t)s1 * HID + lane * 4);
        uint2 u2 = *(const uint2*)(tmp + (size_t)s2 * HID + lane * 4);
        uint2 u3 = *(const uint2*)(tmp + (size_t)s3 * HID + lane * 4);
        float2 a0 = __half22float2(*(half2*)&u0.x), b0 = __half22float2(*(half2*)&u0.y);
        float2 a1 = __half22float2(*(half2*)&u1.x), b1 = __half22float2(*(half2*)&u1.y);
        float2 a2 = __half22float2(*(half2*)&u2.x), b2 = __half22float2(*(half2*)&u2.y);
        float2 a3 = __half22float2(*(half2*)&u3.x), b3 = __half22float2(*(half2*)&u3.y);
        acc.x += a0.x + a1.x + a2.x + a3.x;
        acc.y += a0.y + a1.y + a2.y + a3.y;
        acc.z += b0.x + b1.x + b2.x + b3.x;
        acc.w += b0.y + b1.y + b2.y + b3.y;
    }
    for (; j < cnt; j++) {
        int s = g_col[start + j];
        uint2 u = *(const uint2*)(tmp + (size_t)s * HID + lane * 4);
        float2 a = __half22float2(*(half2*)&u.x), b = __half22float2(*(half2*)&u.y);
        acc.x += a.x; acc.y += a.y; acc.z += b.x; acc.w += b.y;
    }

    float dv = g_dinv[gw];
    float4 b4 = *(const float4*)(bias + lane * 4);
    float4 o;
    o.x = fmaxf(fmaf(acc.x, dv, b4.x), 0.f);
    o.y = fmaxf(fmaf(acc.y, dv, b4.y), 0.f);
    o.z = fmaxf(fmaf(acc.z, dv, b4.z), 0.f);
    o.w = fmaxf(fmaf(acc.w, dv, b4.w), 0.f);

    half2 ha = __floats2half2_rn(o.x, o.y);
    half2 hb = __floats2half2_rn(o.z, o.w);
    uint2 pk;
    pk.x = *(unsigned*)&ha; pk.y = *(unsigned*)&hb;
    if (DST == 0) {
        *(uint2*)(g_h1h + (size_t)gw * HID + lane * 4) = pk;
    } else {
        *(float4*)(outp + (size_t)gw * HID + lane * 4) = o;
        *(uint2*)(g_h2h + (size_t)gw * HID + lane * 4) = pk;
    }
}

// ---------------- head GEMM (HMMA): S[m][c] = h2[m][:] . Wh[:][c] + bh[c] ----------------
// BM=128, N padded 40->48, BK=64 chunks. 8 warps x 16 rows, 6 n-tiles each.
__global__ void __launch_bounds__(256)
k_head(const float* __restrict__ Wh, const float* __restrict__ bh, float* __restrict__ S) {
    __shared__ __align__(16) __half As[128][72];   // 144B row stride
    __shared__ __align__(16) __half Wsh[128][56];  // 112B row stride
    int t = threadIdx.x, lane = t & 31, wid = t >> 5;
    int m0 = blockIdx.x * 128;
    int wm = wid * 16;

    // stage Wh full [128][48] fp16, zero-padded beyond col 40
    for (int i = t; i < 128 * 24; i += 256) {
        int r = i / 24, c2 = (i % 24) * 2;
        float lo = (c2 < NCLS) ? Wh[(size_t)r * NCLS + c2] : 0.f;
        float hi = (c2 + 1 < NCLS) ? Wh[(size_t)r * NCLS + c2 + 1] : 0.f;
        *(half2*)&Wsh[r][c2] = __floats2half2_rn(lo, hi);
    }

    float acc[6][4];
    #pragma unroll
    for (int nt = 0; nt < 6; nt++)
        #pragma unroll
        for (int q = 0; q < 4; q++) acc[nt][q] = 0.f;

    uint32_t as_base = (uint32_t)__cvta_generic_to_shared(&As[0][0]);
    uint32_t ws_base = (uint32_t)__cvta_generic_to_shared(&Wsh[0][0]);
    int a_row = wm + (lane & 15);
    int a_col = (lane >> 4) * 8;
    int g = lane >> 3;
    int b_krow = (lane & 7) + (g >> 1) * 8;
    int b_ncol = (g & 1) * 8;

    #pragma unroll
    for (int kc = 0; kc < HID; kc += 64) {
        // stage h2h chunk [128][64]
        {
            int r = t >> 1, cs = (t & 1) * 32;
            int grow = m0 + r;
            uint4 p0 = make_uint4(0,0,0,0), p1 = p0, p2 = p0, p3 = p0;
            if (grow < NN) {
                const uint4* src = (const uint4*)(g_h2h + (size_t)grow * HID + kc + cs);
                p0 = src[0]; p1 = src[1]; p2 = src[2]; p3 = src[3];
            }
            *(uint4*)&As[r][cs]      = p0;
            *(uint4*)&As[r][cs + 8]  = p1;
            *(uint4*)&As[r][cs + 16] = p2;
            *(uint4*)&As[r][cs + 24] = p3;
        }
        __syncthreads();

        #pragma unroll
        for (int ks = 0; ks < 64; ks += 16) {
            uint32_t a[4];
            ldsm_x4(as_base + (a_row * 72 + ks + a_col) * 2, a[0], a[1], a[2], a[3]);
            uint32_t b[6][2];
            #pragma unroll
            for (int ntq = 0; ntq < 3; ntq++) {
                uint32_t addr = ws_base + ((kc + ks + b_krow) * 56 + b_ncol + ntq * 16) * 2;
                uint32_t r0, r1, r2, r3;
                ldsm_x4_t(addr, r0, r1, r2, r3);
                b[ntq * 2][0] = r0; b[ntq * 2 + 1][0] = r1;
                b[ntq * 2][1] = r2; b[ntq * 2 + 1][1] = r3;
            }
            #pragma unroll
            for (int nt = 0; nt < 6; nt++)
                mma16816(acc[nt], a, b[nt][0], b[nt][1]);
        }
        __syncthreads();
    }

    // epilogue: only cols 0..39 stored
    int qr = lane >> 2, qc = (lane & 3) * 2;
    int row_lo = m0 + wm + qr, row_hi = row_lo + 8;
    #pragma unroll
    for (int nt = 0; nt < 5; nt++) {
        int col = nt * 8 + qc;
        float blo = bh[col], bhi = bh[col + 1];
        if (row_lo < NN) {
            S[(size_t)row_lo * NCLS + col]     = acc[nt][0] + blo;
            S[(size_t)row_lo * NCLS + col + 1] = acc[nt][1] + bhi;
        }
        if (row_hi < NN) {
            S[(size_t)row_hi * NCLS + col]     = acc[nt][2] + blo;
            S[(size_t)row_hi * NCLS + col + 1] = acc[nt][3] + bhi;
        }
    }
}

// ---------------- launch ----------------
extern "C" void kernel_launch(void* const* d_in, const int* in_sizes, int n_in,
                              void* d_out, int out_size) {
    const float* x   = (const float*)d_in[0];
    const void*  ei  = d_in[1];                 // int32 or int64, detected on device
    const float* W1  = (const float*)d_in[2];
    const float* b1  = (const float*)d_in[3];
    const float* W2  = (const float*)d_in[4];
    const float* b2  = (const float*)d_in[5];
    const float* Wh  = (const float*)d_in[6];
    const float* bh  = (const float*)d_in[7];

    float* out = (float*)d_out;
    float* scores = out;                       // [NN, 40]
    float* h2 = out + (size_t)NN * NCLS;       // [NN, 128]

    const int TB = 256;
    int gemm_grid = (NN + 127) / 128;
    int spmm_grid = (NN * 32 + TB - 1) / TB;

    k_init_deg<<<(NN + TB - 1) / TB, TB>>>((const int*)ei);     // 1
    k_count<<<(EE + TB - 1) / TB, TB>>>(ei);                    // 2
    k_dinv<<<(NN + TB - 1) / TB, TB>>>();                       // 3
    k_gemm<0><<<gemm_grid, TB>>>(x, W1);                        // 4  (profiled slot)
    k_scan1<<<NB, TB>>>();                                      // 5
    k_scan2<<<1, 512>>>();                                      // 6
    k_scan3<<<NB, TB>>>();                                      // 7 (+selfloop)
    k_fill<<<(EE + TB - 1) / TB, TB>>>(ei);                     // 8
    k_spmm<0><<<spmm_grid, TB>>>(b1, nullptr);                  // 9
    k_gemm<1><<<gemm_grid, TB>>>(nullptr, W2);                  // 10
    k_spmm<1><<<spmm_grid, TB>>>(b2, h2);                       // 11
    k_head<<<gemm_grid, TB>>>(Wh, bh, scores);                  // 12
}

// round 12
// speedup vs baseline: 1.6219x; 1.0073x over previous
#include <cuda_runtime.h>
#include <cuda_fp16.h>
#include <cstdint>

// Problem constants
#define NN 100000
#define EE 1600000
#define HID 128
#define NCLS 40
#define NB 391              // ceil(NN/256)
#define GG 782              // gemm blocks = ceil(NN/128)

// ---------------- mma.sync / cp.async helpers ----------------
__device__ __forceinline__ void ldsm_x4(uint32_t addr, uint32_t& r0, uint32_t& r1,
                                        uint32_t& r2, uint32_t& r3) {
    asm volatile("ldmatrix.sync.aligned.m8n8.x4.shared.b16 {%0,%1,%2,%3}, [%4];"
                 : "=r"(r0), "=r"(r1), "=r"(r2), "=r"(r3) : "r"(addr));
}
__device__ __forceinline__ void ldsm_x4_t(uint32_t addr, uint32_t& r0, uint32_t& r1,
                                          uint32_t& r2, uint32_t& r3) {
    asm volatile("ldmatrix.sync.aligned.m8n8.x4.trans.shared.b16 {%0,%1,%2,%3}, [%4];"
                 : "=r"(r0), "=r"(r1), "=r"(r2), "=r"(r3) : "r"(addr));
}
__device__ __forceinline__ void mma16816(float c[4], const uint32_t a[4],
                                         uint32_t b0, uint32_t b1) {
    asm volatile(
        "mma.sync.aligned.m16n8k16.row.col.f32.f16.f16.f32 "
        "{%0,%1,%2,%3}, {%4,%5,%6,%7}, {%8,%9}, {%0,%1,%2,%3};"
        : "+f"(c[0]), "+f"(c[1]), "+f"(c[2]), "+f"(c[3])
        : "r"(a[0]), "r"(a[1]), "r"(a[2]), "r"(a[3]), "r"(b0), "r"(b1));
}
__device__ __forceinline__ void cpa16(uint32_t d, const void* s, bool p) {
    asm volatile("cp.async.cg.shared.global [%0], [%1], 16, %2;"
                 :: "r"(d), "l"(s), "r"(p ? 16 : 0));
}
__device__ __forceinline__ void cpcommit() { asm volatile("cp.async.commit_group;"); }

// ---------------- device scratch (static; no cudaMalloc allowed) ----------------
__device__ __half g_xh [(size_t)NN * HID];  // fp16 copy of x
__device__ __half g_w1h[HID * HID];
__device__ __half g_w2h[HID * HID];
__device__ __half g_tmp[(size_t)NN * HID];  // fp16 messages (pre-scaled by dinv[src])
__device__ __half g_h1h[(size_t)NN * HID];  // layer-1 hidden, fp16
__device__ __half g_h2h[(size_t)NN * HID];  // layer-2 hidden, fp16 (head input)
__device__ float  g_dinv[NN];
__device__ int    g_deg[NN];                // in-degree incl self loop
__device__ int    g_rowptr[NN + 1];
__device__ int    g_cursor[NN];
__device__ int    g_col[EE + NN];
__device__ int    g_bsum[512];
__device__ int    g_fmt;                    // 1 = edge_index is int64, 0 = int32

// ---------------- pre-pass: fp16 conversions + deg init + dtype detect ----------------
__global__ void k_pre(const float* __restrict__ x, const float* __restrict__ W1,
                      const float* __restrict__ W2, const int* __restrict__ ei) {
    int i = blockIdx.x * blockDim.x + threadIdx.x;   // grid covers NN*HID/4 = 3.2M
    {
        float4 v = ((const float4*)x)[i];
        half2 a = __floats2half2_rn(v.x, v.y), b = __floats2half2_rn(v.z, v.w);
        uint2 p; p.x = *(unsigned*)&a; p.y = *(unsigned*)&b;
        ((uint2*)g_xh)[i] = p;
    }
    if (i < HID * HID / 4) {
        float4 v = ((const float4*)W1)[i];
        half2 a = __floats2half2_rn(v.x, v.y), b = __floats2half2_rn(v.z, v.w);
        uint2 p; p.x = *(unsigned*)&a; p.y = *(unsigned*)&b;
        ((uint2*)g_w1h)[i] = p;
        float4 w = ((const float4*)W2)[i];
        half2 c = __floats2half2_rn(w.x, w.y), d = __floats2half2_rn(w.z, w.w);
        uint2 q; q.x = *(unsigned*)&c; q.y = *(unsigned*)&d;
        ((uint2*)g_w2h)[i] = q;
    }
    if (i < NN) g_deg[i] = 1;   // self loop
    if (i == 0) {
        int is64 = 1;
        #pragma unroll
        for (int j = 1; j < 64; j += 2) is64 &= (ei[j] == 0);
        g_fmt = is64;
    }
}

__device__ __forceinline__ int edge_at(const void* __restrict__ ei, size_t idx) {
    if (g_fmt) return (int)((const long long*)ei)[idx];
    return ((const int*)ei)[idx];
}

__global__ void k_count(const void* __restrict__ ei) {
    int e = blockIdx.x * blockDim.x + threadIdx.x;
    if (e < EE) {
        int d = edge_at(ei, (size_t)EE + e);
        if ((unsigned)d < NN) atomicAdd(&g_deg[d], 1);
    }
}

// scan1 + dinv fused
__global__ void k_scan1() {
    __shared__ int s[256];
    int b = blockIdx.x, t = threadIdx.x;
    int i = b * 256 + t;
    int v = (i < NN) ? g_deg[i] : 0;
    if (i < NN) g_dinv[i] = rsqrtf((float)v);
    s[t] = v;
    __syncthreads();
    #pragma unroll
    for (int off = 1; off < 256; off <<= 1) {
        int add = (t >= off) ? s[t - off] : 0;
        __syncthreads();
        s[t] += add;
        __syncthreads();
    }
    if (i < NN) g_rowptr[i] = s[t] - v;
    if (t == 255) g_bsum[b] = s[255];
}

__global__ void k_scan2() {
    __shared__ int s[512];
    int t = threadIdx.x;
    int v = (t < NB) ? g_bsum[t] : 0;
    s[t] = v;
    __syncthreads();
    #pragma unroll
    for (int off = 1; off < 512; off <<= 1) {
        int add = (t >= off) ? s[t - off] : 0;
        __syncthreads();
        s[t] += add;
        __syncthreads();
    }
    if (t < NB) g_bsum[t] = s[t] - v;
}

// scan3 + selfloop + cursor init fused
__global__ void k_scan3() {
    int b = blockIdx.x, t = threadIdx.x;
    int i = b * 256 + t;
    if (i < NN) {
        int rp = g_rowptr[i] + g_bsum[b];
        g_rowptr[i] = rp;
        if ((unsigned)rp < (unsigned)(EE + NN)) g_col[rp] = i;   // self loop at slot 0
        g_cursor[i] = 1;
    }
    if (i == 0) g_rowptr[NN] = EE + NN;
}

// ---------------- tensor-core GEMM body (cp.async double-buffered) ----------------
// g_tmp[m][n] = half((A.W)[m][n] * dinv[m]); A fp16 [NN,128], W fp16 [128,128].
__device__ __forceinline__ void gemm_body(const __half* __restrict__ Ah,
                                          const __half* __restrict__ Wm,
                                          int bid, __half* AsBuf, __half* WsBuf) {
    const int ABUF = 128 * 40 * 2;   // bytes per A buffer
    const int WBUF = 32 * 136 * 2;   // bytes per W buffer
    int t = threadIdx.x, lane = t & 31, wid = t >> 5;
    int m0 = bid * 128;
    int wm = (wid & 3) * 32;
    int wn = (wid >> 2) * 64;

    float acc[2][8][4];
    #pragma unroll
    for (int mt = 0; mt < 2; mt++)
        #pragma unroll
        for (int nt = 0; nt < 8; nt++)
            #pragma unroll
            for (int q = 0; q < 4; q++) acc[mt][nt][q] = 0.f;

    uint32_t as_base = (uint32_t)__cvta_generic_to_shared(AsBuf);
    uint32_t ws_base = (uint32_t)__cvta_generic_to_shared(WsBuf);

    // staging: A row sr (80B stride), 2x16B; W row swr (272B stride), 2x16B
    int sr = t >> 1, sseg = (t & 1) * 2;
    int swr = t >> 3, swseg = (t & 7) * 2;
    int sgrow = m0 + sr;
    bool sp = sgrow < NN;
    const __half* aSrc = Ah + (size_t)sgrow * HID + sseg * 8;
    const __half* wSrc = Wm + (size_t)swr * HID + swseg * 8;
    uint32_t aDst = as_base + sr * 80 + sseg * 16;
    uint32_t wDst = ws_base + swr * 272 + swseg * 16;

    // ldmatrix lane addressing
    int a_row = wm + (lane & 15);
    int a_col = (lane >> 4) * 8;
    int g = lane >> 3;
    int b_krow = (lane & 7) + (g >> 1) * 8;
    int b_ncol = wn + (g & 1) * 8;

    // prefetch chunk 0
    cpa16(aDst, aSrc, sp);
    cpa16(aDst + 16, aSrc + 8, sp);
    cpa16(wDst, wSrc, true);
    cpa16(wDst + 16, wSrc + 8, true);
    cpcommit();

    #pragma unroll
    for (int i = 0; i < 4; i++) {
        if (i < 3) {
            int buf = (i + 1) & 1, kc = (i + 1) * 32;
            cpa16(aDst + buf * ABUF, aSrc + kc, sp);
            cpa16(aDst + buf * ABUF + 16, aSrc + kc + 8, sp);
            cpa16(wDst + buf * WBUF, wSrc + (size_t)kc * HID, true);
            cpa16(wDst + buf * WBUF + 16, wSrc + (size_t)kc * HID + 8, true);
            cpcommit();
            asm volatile("cp.async.wait_group 1;" ::: "memory");
        } else {
            asm volatile("cp.async.wait_group 0;" ::: "memory");
        }
        __syncthreads();
        int cur = i & 1;
        uint32_t a_b = as_base + cur * ABUF;
        uint32_t w_b = ws_base + cur * WBUF;

        #pragma unroll
        for (int ks = 0; ks < 32; ks += 16) {
            uint32_t a[2][4];
            #pragma unroll
            for (int mt = 0; mt < 2; mt++) {
                uint32_t addr = a_b + ((a_row + mt * 16) * 40 + ks + a_col) * 2;
                ldsm_x4(addr, a[mt][0], a[mt][1], a[mt][2], a[mt][3]);
            }
            uint32_t b[8][2];
            #pragma unroll
            for (int ntq = 0; ntq < 4; ntq++) {
                uint32_t addr = w_b + ((ks + b_krow) * 136 + b_ncol + ntq * 16) * 2;
                uint32_t r0, r1, r2, r3;
                ldsm_x4_t(addr, r0, r1, r2, r3);
                b[ntq * 2][0] = r0; b[ntq * 2 + 1][0] = r1;
                b[ntq * 2][1] = r2; b[ntq * 2 + 1][1] = r3;
            }
            #pragma unroll
            for (int mt = 0; mt < 2; mt++)
                #pragma unroll
                for (int nt = 0; nt < 8; nt++)
                    mma16816(acc[mt][nt], a[mt], b[nt][0], b[nt][1]);
        }
        __syncthreads();
    }

    // epilogue: scale by dinv[row], convert to fp16, store
    int qr = lane >> 2, qc = (lane & 3) * 2;
    #pragma unroll
    for (int mt = 0; mt < 2; mt++) {
        int row_lo = m0 + wm + mt * 16 + qr;
        int row_hi = row_lo + 8;
        float sc_lo = (row_lo < NN) ? g_dinv[row_lo] : 0.f;
        float sc_hi = (row_hi < NN) ? g_dinv[row_hi] : 0.f;
        #pragma unroll
        for (int nt = 0; nt < 8; nt++) {
            int colg = wn + nt * 8 + qc;
            if (row_lo < NN) {
                half2 h = __floats2half2_rn(acc[mt][nt][0] * sc_lo, acc[mt][nt][1] * sc_lo);
                *(half2*)(g_tmp + (size_t)row_lo * HID + colg) = h;
            }
            if (row_hi < NN) {
                half2 h = __floats2half2_rn(acc[mt][nt][2] * sc_hi, acc[mt][nt][3] * sc_hi);
                *(half2*)(g_tmp + (size_t)row_hi * HID + colg) = h;
            }
        }
    }
}

// fused: blocks [0,GG) = GEMM layer 1 (x.W1); blocks [GG,..) = CSR fill
__global__ void __launch_bounds__(256, 2) k_fillgemm1(const void* __restrict__ ei) {
    __shared__ __align__(16) __half As[2][128][40];
    __shared__ __align__(16) __half Ws[2][32][136];
    if (blockIdx.x < GG) {
        gemm_body(g_xh, g_w1h, blockIdx.x, &As[0][0][0], &Ws[0][0][0]);
    } else {
        int e = (blockIdx.x - GG) * 256 + threadIdx.x;
        if (e < EE) {
            int s = edge_at(ei, e);
            int d = edge_at(ei, (size_t)EE + e);
            if ((unsigned)d < NN) {
                int pos = atomicAdd(&g_cursor[d], 1);
                int w = g_rowptr[d] + pos;
                int c = ((unsigned)s < NN) ? s : d;
                if ((unsigned)w < (unsigned)(EE + NN)) g_col[w] = c;
            }
        }
    }
}

__global__ void __launch_bounds__(256, 2) k_gemm2() {
    __shared__ __align__(16) __half As[2][128][40];
    __shared__ __align__(16) __half Ws[2][32][136];
    gemm_body(g_h1h, g_w2h, blockIdx.x, &As[0][0][0], &Ws[0][0][0]);
}

// ---------------- SpMM: out[d] = relu(dinv[d] * sum_{s in N(d)} g_tmp[s] + bias) ----------------
// DST=0: write fp16 g_h1h only. DST=1: write fp32 outp (h2) + fp16 g_h2h.
template<int DST>
__global__ void k_spmm(const float* __restrict__ bias, float* __restrict__ outp) {
    int gw = (blockIdx.x * blockDim.x + threadIdx.x) >> 5;
    int lane = threadIdx.x & 31;
    if (gw >= NN) return;
    int start = g_rowptr[gw];
    int cnt = g_deg[gw];
    const __half* tmp = (const __half*)g_tmp;

    float4 acc = make_float4(0.f, 0.f, 0.f, 0.f);
    int j = 0;
    for (; j + 4 <= cnt; j += 4) {
        int s0 = g_col[start + j];
        int s1 = g_col[start + j + 1];
        int s2 = g_col[start + j + 2];
        int s3 = g_col[start + j + 3];
        uint2 u0 = *(const uint2*)(tmp + (size_t)s0 * HID + lane * 4);
        uint2 u1 = *(const uint2*)(tmp + (size_t)s1 * HID + lane * 4);
        uint2 u2 = *(const uint2*)(tmp + (size_t)s2 * HID + lane * 4);
        uint2 u3 = *(const uint2*)(tmp + (size_t)s3 * HID + lane * 4);
        float2 a0 = __half22float2(*(half2*)&u0.x), b0 = __half22float2(*(half2*)&u0.y);
        float2 a1 = __half22float2(*(half2*)&u1.x), b1 = __half22float2(*(half2*)&u1.y);
        float2 a2 = __half22float2(*(half2*)&u2.x), b2 = __half22float2(*(half2*)&u2.y);
        float2 a3 = __half22float2(*(half2*)&u3.x), b3 = __half22float2(*(half2*)&u3.y);
        acc.x += a0.x + a1.x + a2.x + a3.x;
        acc.y += a0.y + a1.y + a2.y + a3.y;
        acc.z += b0.x + b1.x + b2.x + b3.x;
        acc.w += b0.y + b1.y + b2.y + b3.y;
    }
    for (; j < cnt; j++) {
        int s = g_col[start + j];
        uint2 u = *(const uint2*)(tmp + (size_t)s * HID + lane * 4);
        float2 a = __half22float2(*(half2*)&u.x), b = __half22float2(*(half2*)&u.y);
        acc.x += a.x; acc.y += a.y; acc.z += b.x; acc.w += b.y;
    }

    float dv = g_dinv[gw];
    float4 b4 = *(const float4*)(bias + lane * 4);
    float4 o;
    o.x = fmaxf(fmaf(acc.x, dv, b4.x), 0.f);
    o.y = fmaxf(fmaf(acc.y, dv, b4.y), 0.f);
    o.z = fmaxf(fmaf(acc.z, dv, b4.z), 0.f);
    o.w = fmaxf(fmaf(acc.w, dv, b4.w), 0.f);

    half2 ha = __floats2half2_rn(o.x, o.y);
    half2 hb = __floats2half2_rn(o.z, o.w);
    uint2 pk;
    pk.x = *(unsigned*)&ha; pk.y = *(unsigned*)&hb;
    if (DST == 0) {
        *(uint2*)(g_h1h + (size_t)gw * HID + lane * 4) = pk;
    } else {
        *(float4*)(outp + (size_t)gw * HID + lane * 4) = o;
        *(uint2*)(g_h2h + (size_t)gw * HID + lane * 4) = pk;
    }
}

// ---------------- head GEMM (HMMA): S[m][c] = h2[m][:] . Wh[:][c] + bh[c] ----------------
__global__ void __launch_bounds__(256)
k_head(const float* __restrict__ Wh, const float* __restrict__ bh, float* __restrict__ S) {
    __shared__ __align__(16) __half As[128][72];
    __shared__ __align__(16) __half Wsh[128][56];
    int t = threadIdx.x, lane = t & 31, wid = t >> 5;
    int m0 = blockIdx.x * 128;
    int wm = wid * 16;

    for (int i = t; i < 128 * 24; i += 256) {
        int r = i / 24, c2 = (i % 24) * 2;
        float lo = (c2 < NCLS) ? Wh[(size_t)r * NCLS + c2] : 0.f;
        float hi = (c2 + 1 < NCLS) ? Wh[(size_t)r * NCLS + c2 + 1] : 0.f;
        *(half2*)&Wsh[r][c2] = __floats2half2_rn(lo, hi);
    }

    float acc[6][4];
    #pragma unroll
    for (int nt = 0; nt < 6; nt++)
        #pragma unroll
        for (int q = 0; q < 4; q++) acc[nt][q] = 0.f;

    uint32_t as_base = (uint32_t)__cvta_generic_to_shared(&As[0][0]);
    uint32_t ws_base = (uint32_t)__cvta_generic_to_shared(&Wsh[0][0]);
    int a_row = wm + (lane & 15);
    int a_col = (lane >> 4) * 8;
    int g = lane >> 3;
    int b_krow = (lane & 7) + (g >> 1) * 8;
    int b_ncol = (g & 1) * 8;

    #pragma unroll
    for (int kc = 0; kc < HID; kc += 64) {
        {
            int r = t >> 1, cs = (t & 1) * 32;
            int grow = m0 + r;
            uint4 p0 = make_uint4(0,0,0,0), p1 = p0, p2 = p0, p3 = p0;
            if (grow < NN) {
                const uint4* src = (const uint4*)(g_h2h + (size_t)grow * HID + kc + cs);
                p0 = src[0]; p1 = src[1]; p2 = src[2]; p3 = src[3];
            }
            *(uint4*)&As[r][cs]      = p0;
            *(uint4*)&As[r][cs + 8]  = p1;
            *(uint4*)&As[r][cs + 16] = p2;
            *(uint4*)&As[r][cs + 24] = p3;
        }
        __syncthreads();

        #pragma unroll
        for (int ks = 0; ks < 64; ks += 16) {
            uint32_t a[4];
            ldsm_x4(as_base + (a_row * 72 + ks + a_col) * 2, a[0], a[1], a[2], a[3]);
            uint32_t b[6][2];
            #pragma unroll
            for (int ntq = 0; ntq < 3; ntq++) {
                uint32_t addr = ws_base + ((kc + ks + b_krow) * 56 + b_ncol + ntq * 16) * 2;
                uint32_t r0, r1, r2, r3;
                ldsm_x4_t(addr, r0, r1, r2, r3);
                b[ntq * 2][0] = r0; b[ntq * 2 + 1][0] = r1;
                b[ntq * 2][1] = r2; b[ntq * 2 + 1][1] = r3;
            }
            #pragma unroll
            for (int nt = 0; nt < 6; nt++)
                mma16816(acc[nt], a, b[nt][0], b[nt][1]);
        }
        __syncthreads();
    }

    int qr = lane >> 2, qc = (lane & 3) * 2;
    int row_lo = m0 + wm + qr, row_hi = row_lo + 8;
    #pragma unroll
    for (int nt = 0; nt < 5; nt++) {
        int col = nt * 8 + qc;
        float blo = bh[col], bhi = bh[col + 1];
        if (row_lo < NN) {
            S[(size_t)row_lo * NCLS + col]     = acc[nt][0] + blo;
            S[(size_t)row_lo * NCLS + col + 1] = acc[nt][1] + bhi;
        }
        if (row_hi < NN) {
            S[(size_t)row_hi * NCLS + col]     = acc[nt][2] + blo;
            S[(size_t)row_hi * NCLS + col + 1] = acc[nt][3] + bhi;
        }
    }
}

// ---------------- launch ----------------
extern "C" void kernel_launch(void* const* d_in, const int* in_sizes, int n_in,
                              void* d_out, int out_size) {
    const float* x   = (const float*)d_in[0];
    const void*  ei  = d_in[1];                 // int32 or int64, detected on device
    const float* W1  = (const float*)d_in[2];
    const float* b1  = (const float*)d_in[3];
    const float* W2  = (const float*)d_in[4];
    const float* b2  = (const float*)d_in[5];
    const float* Wh  = (const float*)d_in[6];
    const float* bh  = (const float*)d_in[7];

    float* out = (float*)d_out;
    float* scores = out;                       // [NN, 40]
    float* h2 = out + (size_t)NN * NCLS;       // [NN, 128]

    const int TB = 256;
    int spmm_grid = (NN * 32 + TB - 1) / TB;
    int fill_blocks = (EE + TB - 1) / TB;      // 6250

    k_pre<<<NN * HID / 4 / TB, TB>>>(x, W1, W2, (const int*)ei);   // 12500 blocks
    k_count<<<(EE + TB - 1) / TB, TB>>>(ei);
    k_scan1<<<NB, TB>>>();                      // + dinv
    k_scan2<<<1, 512>>>();
    k_scan3<<<NB, TB>>>();                      // + selfloop + cursor
    k_fillgemm1<<<GG + fill_blocks, TB>>>(ei);  // GEMM1 || CSR fill
    k_spmm<0><<<spmm_grid, TB>>>(b1, nullptr);
    k_gemm2<<<GG, TB>>>();
    k_spmm<1><<<spmm_grid, TB>>>(b2, h2);
    k_head<<<GG, TB>>>(Wh, bh, scores);
}